// round 6
// baseline (speedup 1.0000x reference)
#include <cuda_runtime.h>
#include <math.h>

#define ROWS_PER_WARP 4
#define THREADS 256
#define ROWS_PER_BLOCK (ROWS_PER_WARP * (THREADS / 32))   // 32

// mean index and variance index of exp-tilted distribution on {0..511}, t = lambda*h.
// c(x) = coth(x) - 1/x. The c(t/2) leg is always |arg|<=0.03 -> pure series (no branch).
__device__ __forceinline__ void moments(float t, float& mu, float& var) {
    float u = 0.5f * t;
    float u2 = u * u;
    float c1 = u * (0.33333334f - u2 * 0.022222223f);       // c(u)
    float cp1 = 0.33333334f - u2 * 0.06666667f;             // c'(u)
    float x = 256.0f * t;                                   // |x| <= ~15.4
    float c, cp;
    if (fabsf(x) < 0.5f) {
        float x2 = x * x;
        c = x * (0.33333334f + x2 * (-0.022222223f + x2 * 0.0021164021f));
        cp = 0.33333334f + x2 * (-0.06666667f + x2 * 0.010582011f);
    } else {
        float e = __expf(2.0f * x);                         // finite: |2x| <= 30.8
        float coth = __fdividef(e + 1.0f, e - 1.0f);
        float ix = __fdividef(1.0f, x);
        c = coth - ix;
        cp = 1.0f - 2.0f * c * ix - c * c;
    }
    mu = 255.5f + 256.0f * c - 0.5f * c1;
    var = 65536.0f * cp - 0.25f * cp1;
}

// log(sinh(x)/x), |x| <= ~15.4
__device__ __forceinline__ float log_sinhc(float x) {
    float ax = fabsf(x);
    if (ax < 0.5f) {
        float x2 = x * x;
        return x2 * (0.16666667f - x2 * 0.0055555556f);
    }
    float s = 0.5f * (__expf(ax) - __expf(-ax));
    return __logf(__fdividef(s, ax));
}

__global__ void __launch_bounds__(THREADS)
fused_kernel(const float* __restrict__ vel, const float* __restrict__ xi,
             float* __restrict__ out, int n) {
    int tid = threadIdx.x;
    int warpid = tid >> 5;
    int lane = tid & 31;
    int rowbase = blockIdx.x * ROWS_PER_BLOCK + warpid * ROWS_PER_WARP;
    if (rowbase >= n) return;

    float h = __ldg(&xi[1]) - __ldg(&xi[0]);      // 70/511, L1-hot

    // ---- Solve: lanes 0..3 each own one row (slim 4-iter Newton) ----
    float lam = 0.0f, mu0 = 0.0f, r = 1.0f, R = 1.0f;
    if (lane < ROWS_PER_WARP && rowbase + lane < n) {
        float target = __fdividef(__ldg(&vel[rowbase + lane]), h);
        // init: inverse Langevin (Cohen) on y = c(256 t), ~5% accurate
        float y = (target - 255.5f) * (1.0f / 256.0f);
        y = fminf(0.92f, fmaxf(-0.92f, y));
        float t = y * __fdividef(3.0f - y * y, 1.0f - y * y) * (1.0f / 256.0f);
        #pragma unroll
        for (int it = 0; it < 4; ++it) {
            float mu, var;
            moments(t, mu, var);
            t -= __fdividef(mu - target, var);
            t = fminf(0.06f, fmaxf(-0.06f, t));
        }
        // logS0 = log512 + 255.5 t + log_sinhc(256t) - log_sinhc(t/2)
        float u = 0.5f * t;
        float logS0 = 6.2383246f + 255.5f * t + log_sinhc(256.0f * t)
                      - u * u * 0.16666667f;
        lam = t / h;
        mu0 = -logS0;
        r = __expf(t);
        R = __expf(128.0f * t);
    }

    // ---- Write: warp streams its 4 rows; lane l owns j = 4l + 128k (coalesced float4)
    // Plain (write-back) stores: .cs streaming hint measurably throttles the L1
    // store path on sm_100a (R2-R5 evidence), and nothing re-reads the output.
    float xiv = __ldg(&xi[lane << 2]);
    #pragma unroll
    for (int rr = 0; rr < ROWS_PER_WARP; ++rr) {
        int row = rowbase + rr;
        if (row >= n) break;
        float lamr = __shfl_sync(0xffffffffu, lam, rr);
        float mu0r = __shfl_sync(0xffffffffu, mu0, rr);
        float rA   = __shfl_sync(0xffffffffu, r,   rr);
        float RA   = __shfl_sync(0xffffffffu, R,   rr);
        float r2 = rA * rA;
        float r3 = r2 * rA;
        float v = __expf(fmaf(lamr, xiv, mu0r));  // anchor per lane
        float4* o = reinterpret_cast<float4*>(out) + (size_t)row * 128;
        #pragma unroll
        for (int k = 0; k < 4; ++k) {
            o[lane + (k << 5)] = make_float4(v, v * rA, v * r2, v * r3);
            v *= RA;
        }
    }
}

extern "C" void kernel_launch(void* const* d_in, const int* in_sizes, int n_in,
                              void* d_out, int out_size) {
    const float* vel = (const float*)d_in[0];
    const float* xi  = (const float*)d_in[1];
    int n = in_sizes[0];
    if (n_in >= 2 && in_sizes[0] < in_sizes[1]) {   // defensive: xi is the small (Q) buffer
        vel = (const float*)d_in[1];
        xi  = (const float*)d_in[0];
        n = in_sizes[1];
    }
    float* out = (float*)d_out;
    int blocks = (n + ROWS_PER_BLOCK - 1) / ROWS_PER_BLOCK;
    fused_kernel<<<blocks, THREADS>>>(vel, xi, out, n);
}

// round 7
// speedup vs baseline: 1.0860x; 1.0860x over previous
#include <cuda_runtime.h>
#include <math.h>

#define THREADS 256

// mean/variance index of exp-tilted distribution on {0..511}, t = lambda*h.
// c(x) = coth(x)-1/x. t is WARP-UNIFORM here -> the branch does not diverge.
__device__ __forceinline__ void moments(float t, float& mu, float& var) {
    float u = 0.5f * t;
    float u2 = u * u;
    float c1 = u * (0.33333334f - u2 * 0.022222223f);       // c(u), |u|<=0.03
    float cp1 = 0.33333334f - u2 * 0.06666667f;             // c'(u)
    float x = 256.0f * t;                                   // |x| <= ~15.4
    float c, cp;
    if (fabsf(x) < 0.5f) {
        float x2 = x * x;
        c = x * (0.33333334f + x2 * (-0.022222223f + x2 * 0.0021164021f));
        cp = 0.33333334f + x2 * (-0.06666667f + x2 * 0.010582011f);
    } else {
        float e = __expf(2.0f * x);                         // finite: |2x| <= 30.8
        float coth = __fdividef(e + 1.0f, e - 1.0f);
        float ix = __fdividef(1.0f, x);
        c = coth - ix;
        cp = 1.0f - 2.0f * c * ix - c * c;
    }
    mu = 255.5f + 256.0f * c - 0.5f * c1;
    var = 65536.0f * cp - 0.25f * cp1;
}

// log(sinh(x)/x), |x| <= ~15.4, warp-uniform branch
__device__ __forceinline__ float log_sinhc(float x) {
    float ax = fabsf(x);
    if (ax < 0.5f) {
        float x2 = x * x;
        return x2 * (0.16666667f - x2 * 0.0055555556f);
    }
    float s = 0.5f * (__expf(ax) - __expf(-ax));
    return __logf(__fdividef(s, ax));
}

// One warp per row. ALL 32 lanes redundantly solve the same row's Newton
// (warp-uniform: same issue cost as 1 active lane, no divergence, no shfl),
// then the warp streams its 512 floats as 4 coalesced float4 per lane.
__global__ void __launch_bounds__(THREADS)
fused_kernel(const float* __restrict__ vel, const float* __restrict__ xi,
             float* __restrict__ out, int n) {
    int warp = (blockIdx.x * THREADS + threadIdx.x) >> 5;
    int lane = threadIdx.x & 31;
    if (warp >= n) return;

    float h = __ldg(&xi[1]) - __ldg(&xi[0]);               // 70/511, L1-hot
    float target = __fdividef(__ldg(&vel[warp]), h);       // broadcast load, 1 sector/warp

    // init: inverse Langevin (Cohen) on y = c(256 t), ~5% accurate
    float y = (target - 255.5f) * (1.0f / 256.0f);
    y = fminf(0.92f, fmaxf(-0.92f, y));
    float t = y * __fdividef(3.0f - y * y, 1.0f - y * y) * (1.0f / 256.0f);
    #pragma unroll
    for (int it = 0; it < 3; ++it) {                       // 5e-2 -> 2.5e-3 -> 6e-6 -> 4e-11
        float mu, var;
        moments(t, mu, var);
        t -= __fdividef(mu - target, var);
        t = fminf(0.06f, fmaxf(-0.06f, t));                // true root |t| <= ~0.028
    }
    // logS0 = log512 + 255.5 t + log_sinhc(256t) - log_sinhc(t/2)
    float u = 0.5f * t;
    float mu0 = -(6.2383246f + 255.5f * t + log_sinhc(256.0f * t)
                  - u * u * 0.16666667f);

    // f[j] = exp(mu0 + t*j). Lane l anchors at j=4l, ladder r,r^2,r^3 in-vector,
    // R = r^128 between the 4 float4 stores. All coalesced 512B wavefronts.
    float r  = __expf(t);
    float R  = __expf(128.0f * t);
    float r2 = r * r;
    float r3 = r2 * r;
    float v = __expf(fmaf(t, (float)(lane << 2), mu0));    // anchor: exact index form
    float4* o = reinterpret_cast<float4*>(out) + (size_t)warp * 128;
    #pragma unroll
    for (int k = 0; k < 4; ++k) {
        o[lane + (k << 5)] = make_float4(v, v * r, v * r2, v * r3);
        v *= R;
    }
}

extern "C" void kernel_launch(void* const* d_in, const int* in_sizes, int n_in,
                              void* d_out, int out_size) {
    const float* vel = (const float*)d_in[0];
    const float* xi  = (const float*)d_in[1];
    int n = in_sizes[0];
    if (n_in >= 2 && in_sizes[0] < in_sizes[1]) {   // defensive: xi is the small (Q) buffer
        vel = (const float*)d_in[1];
        xi  = (const float*)d_in[0];
        n = in_sizes[1];
    }
    float* out = (float*)d_out;
    int warps_per_block = THREADS / 32;
    int blocks = (n + warps_per_block - 1) / warps_per_block;   // 8192 for n=65536
    fused_kernel<<<blocks, THREADS>>>(vel, xi, out, n);
}